// round 11
// baseline (speedup 1.0000x reference)
#include <cuda_runtime.h>

#define NB 16384
#define N1 1024
#define K1 512
#define N2 512
#define K2 1024
#define NCTA 304
#define NPREP 304
#define RPTOT (N1*K1 + N2*K2)        // 1048576 repack elements
#define RPSLICE 3450                 // ceil(RPTOT/304)
#define NT1 1024                     // G1: 128 rowblocks(128) x 8 ntiles
#define NT2 1024                     // G2: 256 rowblocks(64)  x 4 ntiles
#define T1B NPREP
#define T2B (NPREP + NT1)
#define NTILES (NPREP + NT1 + NT2)

// ---------------- device-global scratch (no allocations) -------------------
__device__ float g_W1p[N1 * K1];
__device__ float g_W2p[N2 * K2];
__device__ float g_h[(size_t)NB * N1];
__device__ float g_beff1[N1], g_beff2[N2], g_c[N1];
__device__ int   g_q;
__device__ int   g_prep_done;
__device__ int   g_ready[NB / 128];

// ---------------- init (graph-replay-safe reset) ---------------------------
__global__ void init_k() {
    int i = threadIdx.x;
    if (i == 0) { g_q = 0; g_prep_done = 0; }
    if (i < NB / 128) g_ready[i] = 0;
}

// ---------------- prep slice (runs inside persistent kernel) ---------------
__device__ void prep_slice(int s, int tid, float* cred,
                           const float* __restrict__ t,
                           const float* __restrict__ W1, const float* __restrict__ b1,
                           const float* __restrict__ W2, const float* __restrict__ b2) {
    // 1) weight repack slice
    int end = min((s + 1) * RPSLICE, RPTOT);
    for (int i = s * RPSLICE + tid; i < end; i += 256) {
        if (i < N1 * K1) {
            int n = i >> 9, k = i & 511;
            g_W1p[i] = W1[n * 513 + k];
        } else {
            int j = i - N1 * K1;
            int n = j >> 10, k = j & 1023;
            g_W2p[j] = W2[n * 1025 + k];
        }
    }
    // 2) c vector: 4 j's per slice, 64 threads each, fixed-order reduce
    {
        int jj = s * 4 + (tid >> 6);           // 0..1215
        int ks = tid & 63;
        float p = 0.f;
        if (jj < N1) {
            #pragma unroll
            for (int i = 0; i < 8; i++) {
                int k = ks + 64 * i;
                p += W2[(size_t)k * 1025 + jj] * W1[(size_t)jj * 513 + k];
            }
        }
        cred[(tid >> 6) * 64 + ks] = p;
    }
    __syncthreads();
    if (tid < 4) {
        int jj = s * 4 + tid;
        if (jj < N1) {
            float ssum = 0.f;
            for (int i = 0; i < 64; i++) ssum += cred[tid * 64 + i];
            g_c[jj] = ssum;
            float t0 = t[0];
            g_beff1[jj] = b1[jj] + t0 * W1[(size_t)jj * 513 + 512];
            if (jj < N2) g_beff2[jj] = b2[jj] + t0 * W2[(size_t)jj * 1025 + 1024];
        }
    }
    __syncthreads();
    __threadfence();
    if (tid == 0) atomicAdd(&g_prep_done, 1);
}

// ---------------- G1 tile: 128x128, K=512, relu, out=g_h -------------------
__device__ __forceinline__ void g1_tile(float* As, float* Bs,
                                        const float* __restrict__ z,
                                        int yt, int xt, int tid) {
    const int m0 = yt * 128, n0 = xt * 128;
    const int lrow = tid >> 1, lk4 = (tid & 1) << 2;
    const float* Ap = z      + (size_t)(m0 + lrow) * K1 + lk4;
    const float* Bp = g_W1p  + (size_t)(n0 + lrow) * K1 + lk4;
    const int tx = tid & 15, ty = tid >> 4;

    float acc[8][8];
    #pragma unroll
    for (int i = 0; i < 8; i++)
        #pragma unroll
        for (int j = 0; j < 8; j++) acc[i][j] = 0.f;

    float4 av = *(const float4*)Ap;
    float4 bv = *(const float4*)Bp;

    for (int k0 = 0; k0 < K1; k0 += 8) {
        As[(lk4 + 0) * 128 + lrow] = av.x;
        As[(lk4 + 1) * 128 + lrow] = av.y;
        As[(lk4 + 2) * 128 + lrow] = av.z;
        As[(lk4 + 3) * 128 + lrow] = av.w;
        Bs[(lk4 + 0) * 128 + lrow] = bv.x;
        Bs[(lk4 + 1) * 128 + lrow] = bv.y;
        Bs[(lk4 + 2) * 128 + lrow] = bv.z;
        Bs[(lk4 + 3) * 128 + lrow] = bv.w;
        __syncthreads();
        if (k0 + 8 < K1) {
            av = *(const float4*)(Ap + k0 + 8);
            bv = *(const float4*)(Bp + k0 + 8);
        }
        #pragma unroll
        for (int kk = 0; kk < 8; kk++) {
            float4 a0 = *(const float4*)&As[kk * 128 + ty * 4];
            float4 a1 = *(const float4*)&As[kk * 128 + ty * 4 + 64];
            float4 b0 = *(const float4*)&Bs[kk * 128 + tx * 4];
            float4 b1 = *(const float4*)&Bs[kk * 128 + tx * 4 + 64];
            float a[8] = {a0.x, a0.y, a0.z, a0.w, a1.x, a1.y, a1.z, a1.w};
            float b[8] = {b0.x, b0.y, b0.z, b0.w, b1.x, b1.y, b1.z, b1.w};
            #pragma unroll
            for (int i = 0; i < 8; i++)
                #pragma unroll
                for (int j = 0; j < 8; j++)
                    acc[i][j] += a[i] * b[j];
        }
        __syncthreads();
    }

    const float4 be0 = *(const float4*)(g_beff1 + n0 + tx * 4);
    const float4 be1 = *(const float4*)(g_beff1 + n0 + 64 + tx * 4);
    #pragma unroll
    for (int i = 0; i < 8; i++) {
        int m = m0 + ty * 4 + (i & 3) + ((i >= 4) ? 64 : 0);
        float4 v0, v1;
        v0.x = fmaxf(acc[i][0] + be0.x, 0.f);
        v0.y = fmaxf(acc[i][1] + be0.y, 0.f);
        v0.z = fmaxf(acc[i][2] + be0.z, 0.f);
        v0.w = fmaxf(acc[i][3] + be0.w, 0.f);
        v1.x = fmaxf(acc[i][4] + be1.x, 0.f);
        v1.y = fmaxf(acc[i][5] + be1.y, 0.f);
        v1.z = fmaxf(acc[i][6] + be1.z, 0.f);
        v1.w = fmaxf(acc[i][7] + be1.w, 0.f);
        float* cp = g_h + (size_t)m * N1 + n0 + tx * 4;
        *(float4*)cp        = v0;
        *(float4*)(cp + 64) = v1;
    }
}

// ---------------- G2 tile: 64x128, K=1024, bias, trace on xt==0 -------------
__device__ __forceinline__ void g2_tile(float* As, float* Bs,
                                        float* __restrict__ out,
                                        int yt, int xt, int tid) {
    const int m0 = yt * 64, n0 = xt * 128;
    const int lrow = tid >> 1, lk4 = (tid & 1) << 2;
    const bool aload = (tid < 128);
    const float* Ap = g_h   + (size_t)(m0 + lrow) * K2 + lk4;   // rows 0..63
    const float* Bp = g_W2p + (size_t)(n0 + lrow) * K2 + lk4;   // rows 0..127
    const int tx = tid & 15, ty = tid >> 4;
    const bool do_trace = (xt == 0);

    float acc[4][8];
    #pragma unroll
    for (int i = 0; i < 4; i++)
        #pragma unroll
        for (int j = 0; j < 8; j++) acc[i][j] = 0.f;

    float tr = 0.f;
    float4 av = aload ? *(const float4*)Ap : make_float4(0, 0, 0, 0);
    float4 bv = *(const float4*)Bp;

    for (int k0 = 0; k0 < K2; k0 += 8) {
        if (aload) {
            As[(lk4 + 0) * 64 + lrow] = av.x;
            As[(lk4 + 1) * 64 + lrow] = av.y;
            As[(lk4 + 2) * 64 + lrow] = av.z;
            As[(lk4 + 3) * 64 + lrow] = av.w;
            if (do_trace) {
                const float4 cv = *(const float4*)(g_c + k0 + lk4);
                tr += (av.x > 0.f) ? cv.x : 0.f;
                tr += (av.y > 0.f) ? cv.y : 0.f;
                tr += (av.z > 0.f) ? cv.z : 0.f;
                tr += (av.w > 0.f) ? cv.w : 0.f;
            }
        }
        Bs[(lk4 + 0) * 128 + lrow] = bv.x;
        Bs[(lk4 + 1) * 128 + lrow] = bv.y;
        Bs[(lk4 + 2) * 128 + lrow] = bv.z;
        Bs[(lk4 + 3) * 128 + lrow] = bv.w;
        __syncthreads();
        if (k0 + 8 < K2) {
            if (aload) av = *(const float4*)(Ap + k0 + 8);
            bv = *(const float4*)(Bp + k0 + 8);
        }
        #pragma unroll
        for (int kk = 0; kk < 8; kk++) {
            float4 a0 = *(const float4*)&As[kk * 64 + ty * 4];
            float4 b0 = *(const float4*)&Bs[kk * 128 + tx * 4];
            float4 b1 = *(const float4*)&Bs[kk * 128 + tx * 4 + 64];
            float a[4] = {a0.x, a0.y, a0.z, a0.w};
            float b[8] = {b0.x, b0.y, b0.z, b0.w, b1.x, b1.y, b1.z, b1.w};
            #pragma unroll
            for (int i = 0; i < 4; i++)
                #pragma unroll
                for (int j = 0; j < 8; j++)
                    acc[i][j] += a[i] * b[j];
        }
        __syncthreads();
    }

    const float4 be0 = *(const float4*)(g_beff2 + n0 + tx * 4);
    const float4 be1 = *(const float4*)(g_beff2 + n0 + 64 + tx * 4);
    #pragma unroll
    for (int i = 0; i < 4; i++) {
        int m = m0 + ty * 4 + i;
        float4 v0, v1;
        v0.x = acc[i][0] + be0.x; v0.y = acc[i][1] + be0.y;
        v0.z = acc[i][2] + be0.z; v0.w = acc[i][3] + be0.w;
        v1.x = acc[i][4] + be1.x; v1.y = acc[i][5] + be1.y;
        v1.z = acc[i][6] + be1.z; v1.w = acc[i][7] + be1.w;
        float* cp = out + (size_t)m * N2 + n0 + tx * 4;
        *(float4*)cp        = v0;
        *(float4*)(cp + 64) = v1;
    }
    if (do_trace && aload) {
        float tro = __shfl_xor_sync(0xffffffffu, tr, 1);
        if ((tid & 1) == 0)
            out[(size_t)NB * N2 + (m0 + lrow)] = -(tr + tro);
    }
}

// ---------------- persistent fused kernel ----------------------------------
__global__ void __launch_bounds__(256, 2)
fused(const float* __restrict__ z, float* __restrict__ out,
      const float* __restrict__ t,
      const float* __restrict__ W1, const float* __restrict__ b1,
      const float* __restrict__ W2, const float* __restrict__ b2) {
    __shared__ float As[8 * 128];
    __shared__ float Bs[8 * 128];
    __shared__ int s_t;
    const int tid = threadIdx.x;

    for (;;) {
        __syncthreads();
        if (tid == 0) s_t = atomicAdd(&g_q, 1);
        __syncthreads();
        const int tq = s_t;
        if (tq >= NTILES) return;

        if (tq < NPREP) {
            prep_slice(tq, tid, As, t, W1, b1, W2, b2);
        } else if (tq < T2B) {
            // gate on prep completion
            if (tid == 0)
                while (*(volatile int*)&g_prep_done < NPREP) __nanosleep(40);
            __syncthreads();
            __threadfence();
            const int u = tq - T1B;
            const int yt = u >> 3, xt = u & 7;
            g1_tile(As, Bs, z, yt, xt, tid);
            __threadfence();                  // release h stores
            __syncthreads();
            if (tid == 0) atomicAdd(&g_ready[yt], 1);
        } else {
            const int u = tq - T2B;
            const int yt = u >> 2, xt = u & 3;     // yt: 64-row block 0..255
            if (tid == 0)
                while (*(volatile int*)&g_ready[yt >> 1] < 8) __nanosleep(40);
            __syncthreads();
            __threadfence();                  // acquire h
            g2_tile(As, Bs, out, yt, xt, tid);
        }
    }
}

// ---------------------------------------------------------------------------
extern "C" void kernel_launch(void* const* d_in, const int* in_sizes, int n_in,
                              void* d_out, int out_size) {
    const float* t  = (const float*)d_in[0];
    const float* z  = (const float*)d_in[1];
    // d_in[2] = logp_z (zeros; unused)
    const float* W1 = (const float*)d_in[3];
    const float* b1 = (const float*)d_in[4];
    const float* W2 = (const float*)d_in[5];
    const float* b2 = (const float*)d_in[6];
    float* out = (float*)d_out;   // dz (NB*512) then dlogp (NB)

    init_k<<<1, 256>>>();
    fused<<<NCTA, 256>>>(z, out, t, W1, b1, W2, b2);
}

// round 12
// speedup vs baseline: 1.0421x; 1.0421x over previous
#include <cuda_runtime.h>

#define NB 16384
#define N1 1024
#define K1 512
#define N2 512
#define K2 1024
#define NROWB 128            // 128-row blocks
#define NT1 1024             // gemm1 tiles: 128 rowblocks x 8 ntiles
#define NT2 512              // gemm2 tiles: 128 rowblocks x 4 ntiles
#define NTILES (NT1 + NT2)
#define NCTA 304

// ---------------- device-global scratch (no allocations) -------------------
__device__ float g_W1p[N1 * K1];
__device__ float g_W2p[N2 * K2];
__device__ float g_h[(size_t)NB * N1];
__device__ float g_beff1[N1], g_beff2[N2], g_c[N1];
__device__ float g_cpart[8][N1];
__device__ int   g_q;
__device__ int   g_ready[NROWB];

// ---------------- prep A: weight repack + c partials -----------------------
__global__ void prepA(const float* __restrict__ W1, const float* __restrict__ W2) {
    int bx = blockIdx.x;
    if (bx < 4096) {
        int idx = bx * 256 + threadIdx.x;
        if (idx < N1 * K1) {
            int n = idx >> 9, k = idx & 511;
            g_W1p[idx] = W1[n * 513 + k];
        } else {
            int j = idx - N1 * K1;
            int n = j >> 10, k = j & 1023;
            g_W2p[j] = W2[n * 1025 + k];
        }
    } else {
        int b  = bx - 4096;                  // 0..31
        int jb = b >> 3;
        int kc = b & 7;
        int j  = jb * 256 + threadIdx.x;
        const float* w1r = W1 + (size_t)j * 513 + kc * 64;
        float s = 0.f;
        #pragma unroll 8
        for (int k = 0; k < 64; k++)
            s += W2[(size_t)(kc * 64 + k) * 1025 + j] * w1r[k];
        g_cpart[kc][j] = s;
    }
}

// ---------------- prep B: finalize c + biases, reset queue -----------------
__global__ void prepB(const float* __restrict__ t,
                      const float* __restrict__ W1, const float* __restrict__ b1,
                      const float* __restrict__ W2, const float* __restrict__ b2) {
    int j = blockIdx.x * 256 + threadIdx.x;  // grid 4 -> j < 1024
    float t0 = t[0];
    float s = 0.f;
    #pragma unroll
    for (int k = 0; k < 8; k++) s += g_cpart[k][j];
    g_c[j] = s;
    g_beff1[j] = b1[j] + t0 * W1[(size_t)j * 513 + 512];
    if (j < N2) g_beff2[j] = b2[j] + t0 * W2[(size_t)j * 1025 + 1024];
    if (j < NROWB) g_ready[j] = 0;
    if (j == N1 - 1) g_q = 0;
}

// ---------------- unified 128x128 FFMA tile, double-buffered smem ----------
template<bool RELU, bool TRACE>
__device__ __forceinline__ void gemm_tile(
    float* As, float* Bs,                     // each [2][8*128]
    const float* __restrict__ A, const float* __restrict__ Bw,
    float* __restrict__ outp, const float* __restrict__ bias,
    int K, int LDC, int m0, int n0,
    float* __restrict__ trace_out, int tid)
{
    const int lrow = tid >> 1;
    const int lk4  = (tid & 1) << 2;
    const float* Ap = A  + (size_t)(m0 + lrow) * K + lk4;
    const float* Bp = Bw + (size_t)(n0 + lrow) * K + lk4;
    const int tx = tid & 15;
    const int ty = tid >> 4;

    float acc[8][8];
    #pragma unroll
    for (int i = 0; i < 8; i++)
        #pragma unroll
        for (int j = 0; j < 8; j++) acc[i][j] = 0.f;

    float tr = 0.f;

    // prologue: slab 0 -> buffer 0
    float4 av = *(const float4*)Ap;
    float4 bv = *(const float4*)Bp;
    As[(lk4 + 0) * 128 + lrow] = av.x;
    As[(lk4 + 1) * 128 + lrow] = av.y;
    As[(lk4 + 2) * 128 + lrow] = av.z;
    As[(lk4 + 3) * 128 + lrow] = av.w;
    Bs[(lk4 + 0) * 128 + lrow] = bv.x;
    Bs[(lk4 + 1) * 128 + lrow] = bv.y;
    Bs[(lk4 + 2) * 128 + lrow] = bv.z;
    Bs[(lk4 + 3) * 128 + lrow] = bv.w;
    if (TRACE) {
        const float4 cv = *(const float4*)(g_c + lk4);
        tr += (av.x > 0.f) ? cv.x : 0.f;
        tr += (av.y > 0.f) ? cv.y : 0.f;
        tr += (av.z > 0.f) ? cv.z : 0.f;
        tr += (av.w > 0.f) ? cv.w : 0.f;
    }
    __syncthreads();
    if (8 < K) { av = *(const float4*)(Ap + 8); bv = *(const float4*)(Bp + 8); }

    int cur = 0;
    for (int k0 = 0; k0 < K; k0 += 8) {
        const int nxt = cur ^ 1024;           // float offset of alternate buffer
        if (k0 + 8 < K) {
            // store slab k0+8 into alternate buffer (no conflict with readers of cur)
            As[nxt + (lk4 + 0) * 128 + lrow] = av.x;
            As[nxt + (lk4 + 1) * 128 + lrow] = av.y;
            As[nxt + (lk4 + 2) * 128 + lrow] = av.z;
            As[nxt + (lk4 + 3) * 128 + lrow] = av.w;
            Bs[nxt + (lk4 + 0) * 128 + lrow] = bv.x;
            Bs[nxt + (lk4 + 1) * 128 + lrow] = bv.y;
            Bs[nxt + (lk4 + 2) * 128 + lrow] = bv.z;
            Bs[nxt + (lk4 + 3) * 128 + lrow] = bv.w;
            if (TRACE) {
                const float4 cv = *(const float4*)(g_c + k0 + 8 + lk4);
                tr += (av.x > 0.f) ? cv.x : 0.f;
                tr += (av.y > 0.f) ? cv.y : 0.f;
                tr += (av.z > 0.f) ? cv.z : 0.f;
                tr += (av.w > 0.f) ? cv.w : 0.f;
            }
            if (k0 + 16 < K) {
                av = *(const float4*)(Ap + k0 + 16);
                bv = *(const float4*)(Bp + k0 + 16);
            }
        }
        #pragma unroll
        for (int kk = 0; kk < 8; kk++) {
            float4 a0 = *(const float4*)&As[cur + kk * 128 + ty * 4];
            float4 a1 = *(const float4*)&As[cur + kk * 128 + ty * 4 + 64];
            float4 b0 = *(const float4*)&Bs[cur + kk * 128 + tx * 4];
            float4 b1 = *(const float4*)&Bs[cur + kk * 128 + tx * 4 + 64];
            float a[8] = {a0.x, a0.y, a0.z, a0.w, a1.x, a1.y, a1.z, a1.w};
            float b[8] = {b0.x, b0.y, b0.z, b0.w, b1.x, b1.y, b1.z, b1.w};
            #pragma unroll
            for (int i = 0; i < 8; i++)
                #pragma unroll
                for (int j = 0; j < 8; j++)
                    acc[i][j] += a[i] * b[j];
        }
        __syncthreads();
        cur ^= 1024;
    }

    const float4 be0 = *(const float4*)(bias + n0 + tx * 4);
    const float4 be1 = *(const float4*)(bias + n0 + 64 + tx * 4);
    #pragma unroll
    for (int i = 0; i < 8; i++) {
        int m = m0 + ty * 4 + (i & 3) + ((i >= 4) ? 64 : 0);
        float v[8];
        v[0] = acc[i][0] + be0.x; v[1] = acc[i][1] + be0.y;
        v[2] = acc[i][2] + be0.z; v[3] = acc[i][3] + be0.w;
        v[4] = acc[i][4] + be1.x; v[5] = acc[i][5] + be1.y;
        v[6] = acc[i][6] + be1.z; v[7] = acc[i][7] + be1.w;
        if (RELU) {
            #pragma unroll
            for (int j = 0; j < 8; j++) v[j] = fmaxf(v[j], 0.f);
        }
        float* cp = outp + (size_t)m * LDC + n0 + tx * 4;
        *(float4*)cp        = make_float4(v[0], v[1], v[2], v[3]);
        *(float4*)(cp + 64) = make_float4(v[4], v[5], v[6], v[7]);
    }
    if (TRACE) {
        float tro = __shfl_xor_sync(0xffffffffu, tr, 1);
        if ((tid & 1) == 0)
            trace_out[m0 + lrow] = -(tr + tro);
    }
}

// ---------------- persistent fused kernel ----------------------------------
__global__ void __launch_bounds__(256, 2)
fused(const float* __restrict__ z, float* __restrict__ out) {
    __shared__ float As[2 * 8 * 128];
    __shared__ float Bs[2 * 8 * 128];
    __shared__ int s_t;
    const int tid = threadIdx.x;

    for (;;) {
        __syncthreads();
        if (tid == 0) s_t = atomicAdd(&g_q, 1);
        __syncthreads();
        const int t = s_t;
        if (t >= NTILES) return;

        if (t < NT1) {
            const int yt = t >> 3, xt = t & 7;
            gemm_tile<true, false>(As, Bs, z, g_W1p, g_h, g_beff1,
                                   K1, N1, yt * 128, xt * 128, nullptr, tid);
            __threadfence();                 // release h stores
            __syncthreads();
            if (tid == 0) atomicAdd(&g_ready[yt], 1);
        } else {
            const int u = t - NT1;
            const int yt = u >> 2, xt = u & 3;
            if (tid == 0) {
                while (*(volatile int*)&g_ready[yt] < 8) __nanosleep(40);
            }
            __syncthreads();
            __threadfence();                 // acquire
            if (xt == 0)
                gemm_tile<false, true>(As, Bs, g_h, g_W2p, out, g_beff2,
                                       K2, N2, yt * 128, 0,
                                       out + (size_t)NB * N2, tid);
            else
                gemm_tile<false, false>(As, Bs, g_h, g_W2p, out, g_beff2,
                                        K2, N2, yt * 128, xt * 128, nullptr, tid);
        }
    }
}

// ---------------------------------------------------------------------------
extern "C" void kernel_launch(void* const* d_in, const int* in_sizes, int n_in,
                              void* d_out, int out_size) {
    const float* t  = (const float*)d_in[0];
    const float* z  = (const float*)d_in[1];
    // d_in[2] = logp_z (zeros; unused)
    const float* W1 = (const float*)d_in[3];
    const float* b1 = (const float*)d_in[4];
    const float* W2 = (const float*)d_in[5];
    const float* b2 = (const float*)d_in[6];
    float* out = (float*)d_out;   // dz (NB*512) then dlogp (NB)

    prepA<<<4096 + 32, 256>>>(W1, W2);
    prepB<<<4, 256>>>(t, W1, b1, W2, b2);
    fused<<<NCTA, 256>>>(z, out);
}

// round 13
// speedup vs baseline: 1.1887x; 1.1406x over previous
#include <cuda_runtime.h>

#define NB 16384
#define N1 1024
#define K1 512
#define N2 512
#define K2 1024
#define NCTA 304
#define NPREP 304
#define RPTOT (N1*K1 + N2*K2)        // 1048576 repack elements
#define RPSLICE 3450                 // ceil(RPTOT/304)
#define NT1 1024                     // G1: 128 rowblocks x 8 ntiles (128x128,K512)
#define NT2 512                      // G2 tiles (128x128,K1024) -> 2 halves each
#define T1B  NPREP
#define T2AB (NPREP + NT1)           // G2 halfA region
#define T2BB (NPREP + NT1 + NT2)     // G2 halfB region
#define NTILES (NPREP + NT1 + 2 * NT2)

// ---------------- device-global scratch (no allocations) -------------------
__device__ float g_W1p[N1 * K1];
__device__ float g_W2p[N2 * K2];
__device__ float g_h[(size_t)NB * N1];
__device__ float g_beff1[N1], g_beff2[N2], g_c[N1];
__device__ int   g_q;
__device__ int   g_prep_done;
__device__ int   g_ready[NB / 128];
__device__ int   g_half[NT2];

// ---------------- init (graph-replay-safe reset) ---------------------------
__global__ void init_k() {
    int i = blockIdx.x * 256 + threadIdx.x;
    if (i == 0) { g_q = 0; g_prep_done = 0; }
    if (i < NB / 128) g_ready[i] = 0;
    if (i < NT2) g_half[i] = 0;
}

// ---------------- prep slice (runs inside persistent kernel) ---------------
__device__ void prep_slice(int s, int tid, float* cred,
                           const float* __restrict__ t,
                           const float* __restrict__ W1, const float* __restrict__ b1,
                           const float* __restrict__ W2, const float* __restrict__ b2) {
    // 1) weight repack slice
    int end = min((s + 1) * RPSLICE, RPTOT);
    for (int i = s * RPSLICE + tid; i < end; i += 256) {
        if (i < N1 * K1) {
            int n = i >> 9, k = i & 511;
            g_W1p[i] = W1[n * 513 + k];
        } else {
            int j = i - N1 * K1;
            int n = j >> 10, k = j & 1023;
            g_W2p[j] = W2[n * 1025 + k];
        }
    }
    // 2) c vector: 4 j's per slice, 64 threads each, fixed-order reduce
    {
        int jj = s * 4 + (tid >> 6);
        int ks = tid & 63;
        float p = 0.f;
        if (jj < N1) {
            #pragma unroll
            for (int i = 0; i < 8; i++) {
                int k = ks + 64 * i;
                p += W2[(size_t)k * 1025 + jj] * W1[(size_t)jj * 513 + k];
            }
        }
        cred[(tid >> 6) * 64 + ks] = p;
    }
    __syncthreads();
    if (tid < 4) {
        int jj = s * 4 + tid;
        if (jj < N1) {
            float ssum = 0.f;
            for (int i = 0; i < 64; i++) ssum += cred[tid * 64 + i];
            g_c[jj] = ssum;
            float t0 = t[0];
            g_beff1[jj] = b1[jj] + t0 * W1[(size_t)jj * 513 + 512];
            if (jj < N2) g_beff2[jj] = b2[jj] + t0 * W2[(size_t)jj * 1025 + 1024];
        }
    }
    __syncthreads();
    __threadfence();
    if (tid == 0) atomicAdd(&g_prep_done, 1);
}

// ---------------- unified 128x128 FFMA tile (R10 body, byte-identical loop) -
// MODE 0: relu(acc+bias) -> outp          (G1)
// MODE 1: acc+bias -> outp                (G2 halfA, k 0..Kloop)
// MODE 2: outp += acc                     (G2 halfB)
// TRACE: partial mask@c over this k-range; MODE1 stores +partial, MODE2
// finalizes -(partialA + partialB).
template<int MODE, bool TRACE>
__device__ __forceinline__ void gemm_tile(
    float* As, float* Bs,
    const float* __restrict__ A, const float* __restrict__ Bw,
    float* __restrict__ outp, const float* __restrict__ bias,
    const float* __restrict__ cbase,
    int Kloop, int lda, int ldc, int m0, int n0,
    float* __restrict__ trace_out, int tid)
{
    const int lrow = tid >> 1;
    const int lk4  = (tid & 1) << 2;
    const float* Ap = A  + (size_t)(m0 + lrow) * lda + lk4;
    const float* Bp = Bw + (size_t)(n0 + lrow) * lda + lk4;
    const int tx = tid & 15;
    const int ty = tid >> 4;

    float acc[8][8];
    #pragma unroll
    for (int i = 0; i < 8; i++)
        #pragma unroll
        for (int j = 0; j < 8; j++) acc[i][j] = 0.f;

    float tr = 0.f;
    float4 av = *(const float4*)Ap;
    float4 bv = *(const float4*)Bp;

    for (int k0 = 0; k0 < Kloop; k0 += 8) {
        As[(lk4 + 0) * 128 + lrow] = av.x;
        As[(lk4 + 1) * 128 + lrow] = av.y;
        As[(lk4 + 2) * 128 + lrow] = av.z;
        As[(lk4 + 3) * 128 + lrow] = av.w;
        Bs[(lk4 + 0) * 128 + lrow] = bv.x;
        Bs[(lk4 + 1) * 128 + lrow] = bv.y;
        Bs[(lk4 + 2) * 128 + lrow] = bv.z;
        Bs[(lk4 + 3) * 128 + lrow] = bv.w;

        if (TRACE) {
            const float4 cv = *(const float4*)(cbase + k0 + lk4);
            tr += (av.x > 0.f) ? cv.x : 0.f;
            tr += (av.y > 0.f) ? cv.y : 0.f;
            tr += (av.z > 0.f) ? cv.z : 0.f;
            tr += (av.w > 0.f) ? cv.w : 0.f;
        }
        __syncthreads();
        if (k0 + 8 < Kloop) {
            av = *(const float4*)(Ap + k0 + 8);
            bv = *(const float4*)(Bp + k0 + 8);
        }
        #pragma unroll
        for (int kk = 0; kk < 8; kk++) {
            float4 a0 = *(const float4*)&As[kk * 128 + ty * 4];
            float4 a1 = *(const float4*)&As[kk * 128 + ty * 4 + 64];
            float4 b0 = *(const float4*)&Bs[kk * 128 + tx * 4];
            float4 b1 = *(const float4*)&Bs[kk * 128 + tx * 4 + 64];
            float a[8] = {a0.x, a0.y, a0.z, a0.w, a1.x, a1.y, a1.z, a1.w};
            float b[8] = {b0.x, b0.y, b0.z, b0.w, b1.x, b1.y, b1.z, b1.w};
            #pragma unroll
            for (int i = 0; i < 8; i++)
                #pragma unroll
                for (int j = 0; j < 8; j++)
                    acc[i][j] += a[i] * b[j];
        }
        __syncthreads();
    }

    #pragma unroll
    for (int i = 0; i < 8; i++) {
        int m = m0 + ty * 4 + (i & 3) + ((i >= 4) ? 64 : 0);
        float* cp = outp + (size_t)m * ldc + n0 + tx * 4;
        if (MODE == 2) {
            float4 o0 = *(const float4*)cp;
            float4 o1 = *(const float4*)(cp + 64);
            o0.x += acc[i][0]; o0.y += acc[i][1];
            o0.z += acc[i][2]; o0.w += acc[i][3];
            o1.x += acc[i][4]; o1.y += acc[i][5];
            o1.z += acc[i][6]; o1.w += acc[i][7];
            *(float4*)cp        = o0;
            *(float4*)(cp + 64) = o1;
        } else {
            const float4 be0 = *(const float4*)(bias + n0 + tx * 4);
            const float4 be1 = *(const float4*)(bias + n0 + 64 + tx * 4);
            float v[8];
            v[0] = acc[i][0] + be0.x; v[1] = acc[i][1] + be0.y;
            v[2] = acc[i][2] + be0.z; v[3] = acc[i][3] + be0.w;
            v[4] = acc[i][4] + be1.x; v[5] = acc[i][5] + be1.y;
            v[6] = acc[i][6] + be1.z; v[7] = acc[i][7] + be1.w;
            if (MODE == 0) {
                #pragma unroll
                for (int j = 0; j < 8; j++) v[j] = fmaxf(v[j], 0.f);
            }
            *(float4*)cp        = make_float4(v[0], v[1], v[2], v[3]);
            *(float4*)(cp + 64) = make_float4(v[4], v[5], v[6], v[7]);
        }
    }
    if (TRACE) {
        float tro = __shfl_xor_sync(0xffffffffu, tr, 1);
        if ((tid & 1) == 0) {
            float part = tr + tro;
            if (MODE == 1) trace_out[m0 + lrow] = part;                     // +partialA
            else           trace_out[m0 + lrow] = -(trace_out[m0 + lrow] + part);
        }
    }
}

// ---------------- persistent fused kernel ----------------------------------
__global__ void __launch_bounds__(256, 2)
fused(const float* __restrict__ z, float* __restrict__ out,
      const float* __restrict__ t,
      const float* __restrict__ W1, const float* __restrict__ b1,
      const float* __restrict__ W2, const float* __restrict__ b2) {
    __shared__ float As[8 * 128];
    __shared__ float Bs[8 * 128];
    __shared__ int s_t;
    const int tid = threadIdx.x;
    float* trace_out = out + (size_t)NB * N2;

    for (;;) {
        __syncthreads();
        if (tid == 0) s_t = atomicAdd(&g_q, 1);
        __syncthreads();
        const int tq = s_t;
        if (tq >= NTILES) return;

        if (tq < NPREP) {
            prep_slice(tq, tid, As, t, W1, b1, W2, b2);
        } else if (tq < T2AB) {
            // ---- G1 tile ----
            if (tid == 0)
                while (*(volatile int*)&g_prep_done < NPREP) __nanosleep(40);
            __syncthreads();
            __threadfence();
            const int u = tq - T1B;
            const int yt = u >> 3, xt = u & 7;
            gemm_tile<0, false>(As, Bs, z, g_W1p, g_h, g_beff1, g_c,
                                K1, K1, N1, yt * 128, xt * 128, nullptr, tid);
            __threadfence();                  // release h stores
            __syncthreads();
            if (tid == 0) atomicAdd(&g_ready[yt], 1);
        } else if (tq < T2BB) {
            // ---- G2 halfA: k 0..511, stores acc+bias ----
            const int u = tq - T2AB;
            const int yt = u >> 2, xt = u & 3;
            if (tid == 0)
                while (*(volatile int*)&g_ready[yt] < 8) __nanosleep(40);
            __syncthreads();
            __threadfence();                  // acquire h
            if (xt == 0)
                gemm_tile<1, true>(As, Bs, g_h, g_W2p, out, g_beff2, g_c,
                                   512, K2, N2, yt * 128, 0, trace_out, tid);
            else
                gemm_tile<1, false>(As, Bs, g_h, g_W2p, out, g_beff2, g_c,
                                    512, K2, N2, yt * 128, xt * 128, nullptr, tid);
            __threadfence();                  // release out partials
            __syncthreads();
            if (tid == 0) atomicExch(&g_half[u], 1);
        } else {
            // ---- G2 halfB: k 512..1023, adds into out ----
            const int u = tq - T2BB;
            const int yt = u >> 2, xt = u & 3;
            if (tid == 0)
                while (*(volatile int*)&g_half[u] == 0) __nanosleep(40);
            __syncthreads();
            __threadfence();                  // acquire halfA partials + h
            if (xt == 0)
                gemm_tile<2, true>(As, Bs, g_h + 512, g_W2p + 512, out, g_beff2,
                                   g_c + 512, 512, K2, N2, yt * 128, 0,
                                   trace_out, tid);
            else
                gemm_tile<2, false>(As, Bs, g_h + 512, g_W2p + 512, out, g_beff2,
                                    g_c + 512, 512, K2, N2, yt * 128, xt * 128,
                                    nullptr, tid);
        }
    }
}

// ---------------------------------------------------------------------------
extern "C" void kernel_launch(void* const* d_in, const int* in_sizes, int n_in,
                              void* d_out, int out_size) {
    const float* t  = (const float*)d_in[0];
    const float* z  = (const float*)d_in[1];
    // d_in[2] = logp_z (zeros; unused)
    const float* W1 = (const float*)d_in[3];
    const float* b1 = (const float*)d_in[4];
    const float* W2 = (const float*)d_in[5];
    const float* b2 = (const float*)d_in[6];
    float* out = (float*)d_out;   // dz (NB*512) then dlogp (NB)

    init_k<<<2, 256>>>();
    fused<<<NCTA, 256>>>(z, out, t, W1, b1, W2, b2);
}